// round 11
// baseline (speedup 1.0000x reference)
#include <cuda_runtime.h>
#include <cuda_fp16.h>
#include <cstdint>

#define DIMX     48
#define HID      16
#define CH       8
#define IMG_H    256
#define IMG_W    256
#define HW       65536
#define TILE     32
#define HALO     34
#define NHALO    (HALO*HALO)    /* 1156 */
#define NINNER   (TILE*TILE)    /* 1024 */
#define NTHREADS 256
#define STG_U2   13             /* uint2 stride per staged pixel (12 + pad) */

typedef unsigned long long u64;

// ---- packed f32x2 helpers (sm_103a FFMA2; ptxas never emits from C++) ----
__device__ __forceinline__ u64 f2pack(float lo, float hi) {
    u64 r; asm("mov.b64 %0,{%1,%2};" : "=l"(r) : "f"(lo), "f"(hi)); return r;
}
__device__ __forceinline__ u64 f2bcast(float v) {
    u64 r; asm("mov.b64 %0,{%1,%1};" : "=l"(r) : "f"(v)); return r;
}
__device__ __forceinline__ void f2unpack(u64 v, float& lo, float& hi) {
    asm("mov.b64 {%0,%1},%2;" : "=f"(lo), "=f"(hi) : "l"(v));
}
__device__ __forceinline__ u64 f2fma(u64 a, u64 b, u64 c) {
    u64 d; asm("fma.rn.f32x2 %0,%1,%2,%3;" : "=l"(d) : "l"(a), "l"(b), "l"(c)); return d;
}
__device__ __forceinline__ u64 f2mul(u64 a, u64 b) {
    u64 d; asm("mul.rn.f32x2 %0,%1,%2;" : "=l"(d) : "l"(a), "l"(b)); return d;
}
__device__ __forceinline__ u64 f2add(u64 a, u64 b) {
    u64 d; asm("add.rn.f32x2 %0,%1,%2;" : "=l"(d) : "l"(a), "l"(b)); return d;
}
__device__ __forceinline__ u64 c2(float v) {
    unsigned u = __float_as_uint(v);
    return ((u64)u << 32) | (u64)u;
}

// packed double-value GELU (exact-erf form, A&S 7.1.26 poly; MUFU parts scalar)
__device__ __forceinline__ u64 gelu2(u64 z) {
    u64 arg = f2mul(z, c2(0.70710678118654752f));
    u64 ax  = arg & 0x7FFFFFFF7FFFFFFFULL;
    u64 den = f2fma(ax, c2(0.3275911f), c2(1.0f));
    float d0, d1, t0, t1;
    f2unpack(den, d0, d1);
    asm("rcp.approx.f32 %0,%1;" : "=f"(t0) : "f"(d0));
    asm("rcp.approx.f32 %0,%1;" : "=f"(t1) : "f"(d1));
    u64 t = f2pack(t0, t1);
    u64 p = f2fma(t, c2(1.061405429f), c2(-1.453152027f));
    p = f2fma(t, p, c2(1.421413741f));
    p = f2fma(t, p, c2(-0.284496736f));
    p = f2fma(t, p, c2(0.254829592f));
    p = f2mul(p, t);
    u64 m = f2mul(ax, ax ^ 0x8000000080000000ULL);   // -ax^2
    m = f2mul(m, c2(1.4426950408889634f));
    float m0, m1, e0, e1;
    f2unpack(m, m0, m1);
    asm("ex2.approx.f32 %0,%1;" : "=f"(e0) : "f"(m0));
    asm("ex2.approx.f32 %0,%1;" : "=f"(e1) : "f"(m1));
    u64 e = f2pack(e0, e1);
    u64 r = f2fma(f2mul(p, e), c2(-1.0f), c2(1.0f));
    u64 erf = r | (arg & 0x8000000080000000ULL);
    u64 h = f2mul(z, c2(0.5f));
    return f2fma(h, erf, h);
}

__device__ __forceinline__ unsigned pack_h2(float a, float b) {
    __half2 h = __floats2half2_rn(a, b);
    return *reinterpret_cast<unsigned*>(&h);
}
__device__ __forceinline__ float2 unpack_h2(unsigned u) {
    __half2 h = *reinterpret_cast<__half2*>(&u);
    return __half22float2(h);
}

extern __shared__ float sm[];

__global__ void __launch_bounds__(NTHREADS, 3) dclf_fused_kernel(
    const float* __restrict__ x,   const float* __restrict__ W1,  const float* __restrict__ b1,
    const float* __restrict__ gam, const float* __restrict__ bet,
    const float* __restrict__ dww, const float* __restrict__ dwb,
    const float* __restrict__ pww, const float* __restrict__ pwb,
    const float* __restrict__ W2,  const float* __restrict__ b2,
    float* __restrict__ out)
{
    // ---- SMEM carve (all segments 16B aligned) ----
    float* sW1  = sm;            // 768  [k*16+j]
    float* sb1  = sW1  + 768;    // 16
    float* sGa  = sb1  + 16;     // 8
    float* sBe  = sGa  + 8;      // 8
    float* sDwT = sBe  + 8;      // 72  [tap*8 + c]
    float* sDwB = sDwT + 72;     // 8
    float* sPwT = sDwB + 8;      // 64  [ci*8 + co]
    float* sPwB = sPwT + 64;     // 8
    float* sW2p = sPwB + 8;      // 384 [dpair*16 + c*2 + h]
    float* sb2  = sW2p + 384;    // 48          -> 1384 floats (5536 B)
    uint4* sNh  = (uint4*)(sb2 + 48);     // 1156 halo n, 8ch fp16 (16 B/px)
    uint4* sX1h = sNh + NHALO;            // 1024 x1, 8ch fp16
    uint2* sStg = (uint2*)(sX1h + NINNER);// 8 warps * 32 px * 13 uint2 (fp16 x)

    const int tid  = threadIdx.x;
    const int warp = tid >> 5, lane = tid & 31;
    const int bx = blockIdx.x, by = blockIdx.y, bb = blockIdx.z;

    // ---- load / relayout weights ----
    for (int i = tid; i < 768; i += NTHREADS) sW1[i] = W1[i];
    if (tid < 16) sb1[tid] = b1[tid];
    if (tid < 8) { sGa[tid] = gam[tid]; sBe[tid] = bet[tid]; sDwB[tid] = dwb[tid]; sPwB[tid] = pwb[tid]; }
    if (tid < 72) sDwT[(tid % 9) * 8 + tid / 9] = dww[tid];        // [c][3][3] -> [tap][c]
    if (tid < 64) sPwT[(tid % 8) * 8 + tid / 8] = pww[tid];        // [co][ci] -> [ci][co]
    for (int i = tid; i < 384; i += NTHREADS) {
        int dp = i >> 4, rem = i & 15, c = rem >> 1, h = rem & 1;
        sW2p[i] = W2[c * DIMX + dp * 2 + h];                       // W2[c][d] -> [dp][c-pairs]
    }
    if (tid < 48) sb2[tid] = b2[tid];
    __syncthreads();

    const int y0 = by * TILE - 1;
    const int x0 = bx * TILE - 1;
    const float* xb = x + (size_t)bb * ((size_t)HW * DIMX);

    uint2* buf = sStg + warp * (32 * STG_U2);

    // ---- Stage A: fp16-staged coalesced loads + packed GEMM1 + gelu2 + LN ----
    // 37 chunks of 32 halo pixels; warp w handles chunks w, w+8, ...
    for (int it = 0; it < 5; ++it) {
        int k = it * 8 + warp;
        if (k > 36) break;
        int q0 = k * 32;
        int qend = min(q0 + 32, NHALO);

        // coalesced chunk load (fp16-converted)
        {
            int r0 = q0 / HALO, r1 = (qend - 1) / HALO;
            #pragma unroll 1
            for (int r = r0; r <= r1; ++r) {
                int gy = y0 + r;
                if ((unsigned)gy < (unsigned)IMG_H) {
                    int qs = max(q0, r * HALO), qe = min(qend, r * HALO + HALO);
                    int gxs = x0 + (qs - r * HALO);
                    int gxe = x0 + (qe - r * HALO);
                    int cs = max(gxs, 0), ce = min(gxe, IMG_W);
                    if (ce > cs) {
                        int bofs = (qs - q0) + (cs - gxs);
                        const float4* gp = (const float4*)(xb + ((size_t)gy * IMG_W + cs) * DIMX);
                        int nf = (ce - cs) * 12;
                        for (int t = lane; t < nf; t += 32) {
                            float4 g = gp[t];
                            uint2 v;
                            v.x = pack_h2(g.x, g.y);
                            v.y = pack_h2(g.z, g.w);
                            buf[(bofs + t / 12) * STG_U2 + (t % 12)] = v;
                        }
                    }
                }
            }
        }
        __syncwarp();

        int q = q0 + lane;
        if (q < qend) {
            int qy = q / HALO, qx = q - qy * HALO;
            int gy = y0 + qy, gx = x0 + qx;
            bool inimg = (gy >= 0) && (gy < IMG_H) && (gx >= 0) && (gx < IMG_W);
            uint4 nv4 = make_uint4(0u, 0u, 0u, 0u);
            if (inimg) {
                const uint2* __restrict__ xp = buf + lane * STG_U2;
                u64 acc[8];
                #pragma unroll
                for (int jj = 0; jj < 8; jj++) acc[jj] = ((const u64*)sb1)[jj];
                #pragma unroll 3
                for (int i = 0; i < 12; i++) {
                    uint2 uxv = xp[i];
                    float2 f0 = unpack_h2(uxv.x), f1 = unpack_h2(uxv.y);
                    const ulonglong2* wr = (const ulonglong2*)&sW1[i * 64];
                    u64 xv;
                    xv = f2bcast(f0.x);
                    #pragma unroll
                    for (int jj = 0; jj < 4; jj++) { ulonglong2 w = wr[jj];      acc[2*jj] = f2fma(xv, w.x, acc[2*jj]); acc[2*jj+1] = f2fma(xv, w.y, acc[2*jj+1]); }
                    xv = f2bcast(f0.y);
                    #pragma unroll
                    for (int jj = 0; jj < 4; jj++) { ulonglong2 w = wr[4 + jj];  acc[2*jj] = f2fma(xv, w.x, acc[2*jj]); acc[2*jj+1] = f2fma(xv, w.y, acc[2*jj+1]); }
                    xv = f2bcast(f1.x);
                    #pragma unroll
                    for (int jj = 0; jj < 4; jj++) { ulonglong2 w = wr[8 + jj];  acc[2*jj] = f2fma(xv, w.x, acc[2*jj]); acc[2*jj+1] = f2fma(xv, w.y, acc[2*jj+1]); }
                    xv = f2bcast(f1.y);
                    #pragma unroll
                    for (int jj = 0; jj < 4; jj++) { ulonglong2 w = wr[12 + jj]; acc[2*jj] = f2fma(xv, w.x, acc[2*jj]); acc[2*jj+1] = f2fma(xv, w.y, acc[2*jj+1]); }
                }
                #pragma unroll
                for (int jj = 0; jj < 8; jj++) acc[jj] = gelu2(gelu2(acc[jj]));

                // LayerNorm over channels 8..15 (= acc[4..7])
                u64 s2 = f2add(f2add(acc[4], acc[5]), f2add(acc[6], acc[7]));
                float sa, sb_; f2unpack(s2, sa, sb_);
                float mmean = (sa + sb_) * 0.125f;
                u64 m2 = f2bcast(mmean);
                u64 d2[4];
                u64 v2 = 0ULL;
                #pragma unroll
                for (int jj = 0; jj < 4; jj++) { d2[jj] = f2fma(m2, c2(-1.0f), acc[4 + jj]); v2 = f2fma(d2[jj], d2[jj], v2); }
                float va, vb; f2unpack(v2, va, vb);
                float rstd = rsqrtf(fmaf(va + vb, 0.125f, 1e-5f));
                u64 r2 = f2bcast(rstd);
                float n0, n1;
                #pragma unroll
                for (int jj = 0; jj < 4; jj++) {
                    u64 nj = f2fma(f2mul(d2[jj], r2), ((const u64*)sGa)[jj], ((const u64*)sBe)[jj]);
                    f2unpack(nj, n0, n1);
                    (&nv4.x)[jj] = pack_h2(n0, n1);
                }
                if (qy >= 1 && qy <= TILE && qx >= 1 && qx <= TILE) {
                    int ip = (qy - 1) * TILE + (qx - 1);
                    float a0, a1; uint4 u;
                    f2unpack(acc[0], a0, a1); u.x = pack_h2(a0, a1);
                    f2unpack(acc[1], a0, a1); u.y = pack_h2(a0, a1);
                    f2unpack(acc[2], a0, a1); u.z = pack_h2(a0, a1);
                    f2unpack(acc[3], a0, a1); u.w = pack_h2(a0, a1);
                    sX1h[ip] = u;
                }
            }
            sNh[q] = nv4;
        }
        __syncwarp();
    }
    __syncthreads();

    // ---- Stage B: per-pixel dw(3x3, fp16 halo) + pw + gate + packed GEMM2 ----
    const int px = tid & 31;
    const int sy = tid >> 5;
    float* outb = out + (size_t)bb * ((size_t)DIMX * HW);
    const u64* dwbU = (const u64*)sDwB;
    const u64* pwbU = (const u64*)sPwB;
    const u64* sb2U = (const u64*)sb2;

    #pragma unroll 1
    for (int r = 0; r < 4; ++r) {
        int py = sy * 4 + r;
        u64 s0 = dwbU[0], s1 = dwbU[1], s2 = dwbU[2], s3 = dwbU[3];
        float n[8];
        #pragma unroll
        for (int dy = 0; dy < 3; dy++) {
            #pragma unroll
            for (int dx = 0; dx < 3; dx++) {
                uint4 tv = sNh[(py + dy) * HALO + (px + dx)];
                float2 f0 = unpack_h2(tv.x), f1 = unpack_h2(tv.y);
                float2 f2v = unpack_h2(tv.z), f3 = unpack_h2(tv.w);
                if (dy == 1 && dx == 1) {
                    n[0] = f0.x; n[1] = f0.y; n[2] = f1.x; n[3] = f1.y;
                    n[4] = f2v.x; n[5] = f2v.y; n[6] = f3.x; n[7] = f3.y;
                }
                const ulonglong2* wt = (const ulonglong2*)&sDwT[(dy * 3 + dx) * 8];
                ulonglong2 wa = wt[0], wb = wt[1];
                s0 = f2fma(f2pack(f0.x, f0.y),  wa.x, s0);
                s1 = f2fma(f2pack(f1.x, f1.y),  wa.y, s1);
                s2 = f2fma(f2pack(f2v.x, f2v.y), wb.x, s2);
                s3 = f2fma(f2pack(f3.x, f3.y),  wb.y, s3);
            }
        }
        // pointwise conv (co-pairs packed)
        u64 chv0 = pwbU[0], chv1 = pwbU[1], chv2 = pwbU[2], chv3 = pwbU[3];
        #pragma unroll
        for (int ci = 0; ci < 8; ++ci) {
            u64 nb_ = f2bcast(n[ci]);
            const ulonglong2* pwr = (const ulonglong2*)&sPwT[ci * 8];
            ulonglong2 w0 = pwr[0], w1 = pwr[1];
            chv0 = f2fma(nb_, w0.x, chv0);
            chv1 = f2fma(nb_, w0.y, chv1);
            chv2 = f2fma(nb_, w1.x, chv2);
            chv3 = f2fma(nb_, w1.y, chv3);
        }
        // gate -> broadcast-packed g[8]
        u64 g[8];
        {
            uint4 u = sX1h[py * TILE + px];
            float2 f; u64 g2v; float ga, gbh;
            f = unpack_h2(u.x); g2v = f2mul(f2pack(f.x, f.y), f2mul(s0, chv0));
            f2unpack(g2v, ga, gbh); g[0] = f2bcast(ga); g[1] = f2bcast(gbh);
            f = unpack_h2(u.y); g2v = f2mul(f2pack(f.x, f.y), f2mul(s1, chv1));
            f2unpack(g2v, ga, gbh); g[2] = f2bcast(ga); g[3] = f2bcast(gbh);
            f = unpack_h2(u.z); g2v = f2mul(f2pack(f.x, f.y), f2mul(s2, chv2));
            f2unpack(g2v, ga, gbh); g[4] = f2bcast(ga); g[5] = f2bcast(gbh);
            f = unpack_h2(u.w); g2v = f2mul(f2pack(f.x, f.y), f2mul(s3, chv3));
            f2unpack(g2v, ga, gbh); g[6] = f2bcast(ga); g[7] = f2bcast(gbh);
        }

        // packed GEMM2 (d-pairs), per pixel
        float* op0 = outb + (size_t)((y0 + 1 + py) * IMG_W + (x0 + 1 + px));
        #pragma unroll 6
        for (int dp = 0; dp < 24; ++dp) {
            const ulonglong2* wv = (const ulonglong2*)&sW2p[dp * 16];
            ulonglong2 w0 = wv[0], w1 = wv[1], w2v = wv[2], w3 = wv[3];
            u64 a = sb2U[dp];
            a = f2fma(g[0], w0.x,  a);
            a = f2fma(g[1], w0.y,  a);
            a = f2fma(g[2], w1.x,  a);
            a = f2fma(g[3], w1.y,  a);
            a = f2fma(g[4], w2v.x, a);
            a = f2fma(g[5], w2v.y, a);
            a = f2fma(g[6], w3.x,  a);
            a = f2fma(g[7], w3.y,  a);
            float v0, v1; f2unpack(a, v0, v1);
            float* od = op0 + (size_t)(dp * 2) * HW;
            od[0]  = v0;
            od[HW] = v1;
        }
    }
}

extern "C" void kernel_launch(void* const* d_in, const int* in_sizes, int n_in,
                              void* d_out, int out_size) {
    (void)in_sizes; (void)n_in; (void)out_size;
    const float* x   = (const float*)d_in[0];
    const float* W1  = (const float*)d_in[1];
    const float* b1  = (const float*)d_in[2];
    const float* gam = (const float*)d_in[3];
    const float* bet = (const float*)d_in[4];
    const float* dww = (const float*)d_in[5];
    const float* dwb = (const float*)d_in[6];
    const float* pww = (const float*)d_in[7];
    const float* pwb = (const float*)d_in[8];
    const float* W2  = (const float*)d_in[9];
    const float* b2  = (const float*)d_in[10];
    float* out = (float*)d_out;

    const int smem_bytes = 1384 * 4                      // weights (5536)
                         + NHALO * 16                    // sNh fp16 (18496)
                         + NINNER * 16                   // sX1h fp16 (16384)
                         + 8 * 32 * STG_U2 * 8;          // staging fp16 (26624)
                                                         // total 67040 B -> 3 CTA/SM
    cudaFuncSetAttribute(dclf_fused_kernel,
                         cudaFuncAttributeMaxDynamicSharedMemorySize, smem_bytes);

    dim3 grid(IMG_W / TILE, IMG_H / TILE, 16);  // 8 x 8 x B
    dclf_fused_kernel<<<grid, NTHREADS, smem_bytes>>>(
        x, W1, b1, gam, bet, dww, dwb, pww, pwb, W2, b2, out);
}

// round 12
// speedup vs baseline: 1.2261x; 1.2261x over previous
#include <cuda_runtime.h>
#include <cuda_fp16.h>
#include <cstdint>

#define DIMX     48
#define HID      16
#define CH       8
#define IMG_H    256
#define IMG_W    256
#define HW       65536
#define TILE     32
#define HALO     34
#define NHALO    (HALO*HALO)    /* 1156 */
#define NINNER   (TILE*TILE)    /* 1024 */
#define NTHREADS 256
#define STG_U2   13             /* uint2 stride per staged pixel (12 + pad) */

typedef unsigned long long u64;

// ---- packed f32x2 helpers (sm_103a FFMA2; ptxas never emits from C++) ----
__device__ __forceinline__ u64 f2pack(float lo, float hi) {
    u64 r; asm("mov.b64 %0,{%1,%2};" : "=l"(r) : "f"(lo), "f"(hi)); return r;
}
__device__ __forceinline__ u64 f2bcast(float v) {
    u64 r; asm("mov.b64 %0,{%1,%1};" : "=l"(r) : "f"(v)); return r;
}
__device__ __forceinline__ void f2unpack(u64 v, float& lo, float& hi) {
    asm("mov.b64 {%0,%1},%2;" : "=f"(lo), "=f"(hi) : "l"(v));
}
__device__ __forceinline__ u64 f2fma(u64 a, u64 b, u64 c) {
    u64 d; asm("fma.rn.f32x2 %0,%1,%2,%3;" : "=l"(d) : "l"(a), "l"(b), "l"(c)); return d;
}
__device__ __forceinline__ u64 f2mul(u64 a, u64 b) {
    u64 d; asm("mul.rn.f32x2 %0,%1,%2;" : "=l"(d) : "l"(a), "l"(b)); return d;
}
__device__ __forceinline__ u64 f2add(u64 a, u64 b) {
    u64 d; asm("add.rn.f32x2 %0,%1,%2;" : "=l"(d) : "l"(a), "l"(b)); return d;
}
__device__ __forceinline__ u64 c2(float v) {
    unsigned u = __float_as_uint(v);
    return ((u64)u << 32) | (u64)u;
}

// packed double-value GELU (exact-erf form, A&S 7.1.26 poly; MUFU parts scalar)
__device__ __forceinline__ u64 gelu2(u64 z) {
    u64 arg = f2mul(z, c2(0.70710678118654752f));
    u64 ax  = arg & 0x7FFFFFFF7FFFFFFFULL;
    u64 den = f2fma(ax, c2(0.3275911f), c2(1.0f));
    float d0, d1, t0, t1;
    f2unpack(den, d0, d1);
    asm("rcp.approx.f32 %0,%1;" : "=f"(t0) : "f"(d0));
    asm("rcp.approx.f32 %0,%1;" : "=f"(t1) : "f"(d1));
    u64 t = f2pack(t0, t1);
    u64 p = f2fma(t, c2(1.061405429f), c2(-1.453152027f));
    p = f2fma(t, p, c2(1.421413741f));
    p = f2fma(t, p, c2(-0.284496736f));
    p = f2fma(t, p, c2(0.254829592f));
    p = f2mul(p, t);
    u64 m = f2mul(ax, ax ^ 0x8000000080000000ULL);   // -ax^2
    m = f2mul(m, c2(1.4426950408889634f));
    float m0, m1, e0, e1;
    f2unpack(m, m0, m1);
    asm("ex2.approx.f32 %0,%1;" : "=f"(e0) : "f"(m0));
    asm("ex2.approx.f32 %0,%1;" : "=f"(e1) : "f"(m1));
    u64 e = f2pack(e0, e1);
    u64 r = f2fma(f2mul(p, e), c2(-1.0f), c2(1.0f));
    u64 erf = r | (arg & 0x8000000080000000ULL);
    u64 h = f2mul(z, c2(0.5f));
    return f2fma(h, erf, h);
}

__device__ __forceinline__ unsigned pack_h2(float a, float b) {
    __half2 h = __floats2half2_rn(a, b);
    return *reinterpret_cast<unsigned*>(&h);
}
__device__ __forceinline__ float2 unpack_h2(unsigned u) {
    __half2 h = *reinterpret_cast<__half2*>(&u);
    return __half22float2(h);
}

// coalesced fp16 staging of one 32-px halo chunk into per-warp buffer slots
__device__ __forceinline__ void stage_chunk(uint2* buf, const float* xb,
                                            int y0, int x0, int q0, int qend,
                                            int slot0, int lane)
{
    int r0 = q0 / HALO, r1 = (qend - 1) / HALO;
    #pragma unroll 1
    for (int r = r0; r <= r1; ++r) {
        int gy = y0 + r;
        if ((unsigned)gy < (unsigned)IMG_H) {
            int qs = max(q0, r * HALO), qe = min(qend, r * HALO + HALO);
            int gxs = x0 + (qs - r * HALO);
            int gxe = x0 + (qe - r * HALO);
            int cs = max(gxs, 0), ce = min(gxe, IMG_W);
            if (ce > cs) {
                int bofs = slot0 + (qs - q0) + (cs - gxs);
                const float4* gp = (const float4*)(xb + ((size_t)gy * IMG_W + cs) * DIMX);
                int nf = (ce - cs) * 12;
                for (int t = lane; t < nf; t += 32) {
                    float4 g = gp[t];
                    uint2 v;
                    v.x = pack_h2(g.x, g.y);
                    v.y = pack_h2(g.z, g.w);
                    buf[(bofs + t / 12) * STG_U2 + (t % 12)] = v;
                }
            }
        }
    }
}

// per-pixel Stage-A epilogue: double-GELU + LN + halo/x1 stores
__device__ __forceinline__ void epilogueA(u64* acc, int q, int y0, int x0,
                                          ulonglong2* sNa, ulonglong2* sNb, uint4* sX1h,
                                          const float* sGa, const float* sBe)
{
    int qy = q / HALO, qx = q - qy * HALO;
    int gy = y0 + qy, gx = x0 + qx;
    bool inimg = (gy >= 0) && (gy < IMG_H) && (gx >= 0) && (gx < IMG_W);
    ulonglong2 na = make_ulonglong2(0ULL, 0ULL);
    ulonglong2 nb = make_ulonglong2(0ULL, 0ULL);
    if (inimg) {
        u64 a8[8];
        #pragma unroll
        for (int jj = 0; jj < 8; jj++) a8[jj] = gelu2(gelu2(acc[jj]));

        // LayerNorm over channels 8..15 (= a8[4..7])
        u64 s2 = f2add(f2add(a8[4], a8[5]), f2add(a8[6], a8[7]));
        float sa, sb_; f2unpack(s2, sa, sb_);
        float mmean = (sa + sb_) * 0.125f;
        u64 m2 = f2bcast(mmean);
        u64 d2[4];
        u64 v2 = 0ULL;
        #pragma unroll
        for (int jj = 0; jj < 4; jj++) { d2[jj] = f2fma(m2, c2(-1.0f), a8[4 + jj]); v2 = f2fma(d2[jj], d2[jj], v2); }
        float va, vb; f2unpack(v2, va, vb);
        float rstd = rsqrtf(fmaf(va + vb, 0.125f, 1e-5f));
        u64 r2 = f2bcast(rstd);
        u64 n2[4];
        #pragma unroll
        for (int jj = 0; jj < 4; jj++)
            n2[jj] = f2fma(f2mul(d2[jj], r2), ((const u64*)sGa)[jj], ((const u64*)sBe)[jj]);
        na = make_ulonglong2(n2[0], n2[1]);
        nb = make_ulonglong2(n2[2], n2[3]);

        if (qy >= 1 && qy <= TILE && qx >= 1 && qx <= TILE) {
            int ip = (qy - 1) * TILE + (qx - 1);
            float a0, a1; uint4 u;
            f2unpack(a8[0], a0, a1); u.x = pack_h2(a0, a1);
            f2unpack(a8[1], a0, a1); u.y = pack_h2(a0, a1);
            f2unpack(a8[2], a0, a1); u.z = pack_h2(a0, a1);
            f2unpack(a8[3], a0, a1); u.w = pack_h2(a0, a1);
            sX1h[ip] = u;
        }
    }
    sNa[q] = na;
    sNb[q] = nb;
}

extern __shared__ float sm[];

__global__ void __launch_bounds__(NTHREADS, 2) dclf_fused_kernel(
    const float* __restrict__ x,   const float* __restrict__ W1,  const float* __restrict__ b1,
    const float* __restrict__ gam, const float* __restrict__ bet,
    const float* __restrict__ dww, const float* __restrict__ dwb,
    const float* __restrict__ pww, const float* __restrict__ pwb,
    const float* __restrict__ W2,  const float* __restrict__ b2,
    float* __restrict__ out)
{
    // ---- SMEM carve (all segments 16B aligned) ----
    float* sW1  = sm;            // 768  [k*16+j]
    float* sb1  = sW1  + 768;    // 16
    float* sGa  = sb1  + 16;     // 8
    float* sBe  = sGa  + 8;      // 8
    float* sDwT = sBe  + 8;      // 72  [tap*8 + c]
    float* sDwB = sDwT + 72;     // 8
    float* sPwT = sDwB + 8;      // 64  [ci*8 + co]
    float* sPwB = sPwT + 64;     // 8
    float* sW2p = sPwB + 8;      // 384 [dpair*16 + c*2 + h]
    float* sb2  = sW2p + 384;    // 48          -> 1384 floats (5536 B)
    ulonglong2* sNa  = (ulonglong2*)(sb2 + 48);  // 1156 fp32 n ch0..3
    ulonglong2* sNb  = sNa + NHALO;              // 1156 fp32 n ch4..7
    uint4*      sX1h = (uint4*)(sNb + NHALO);    // 1024 x1 fp16
    uint2*      sStg = (uint2*)(sX1h + NINNER);  // 8 warps * 64 px * 13 uint2 (fp16 x)

    const int tid  = threadIdx.x;
    const int warp = tid >> 5, lane = tid & 31;
    const int bx = blockIdx.x, by = blockIdx.y, bb = blockIdx.z;

    // ---- load / relayout weights ----
    for (int i = tid; i < 768; i += NTHREADS) sW1[i] = W1[i];
    if (tid < 16) sb1[tid] = b1[tid];
    if (tid < 8) { sGa[tid] = gam[tid]; sBe[tid] = bet[tid]; sDwB[tid] = dwb[tid]; sPwB[tid] = pwb[tid]; }
    if (tid < 72) sDwT[(tid % 9) * 8 + tid / 9] = dww[tid];        // [c][3][3] -> [tap][c]
    if (tid < 64) sPwT[(tid % 8) * 8 + tid / 8] = pww[tid];        // [co][ci] -> [ci][co]
    for (int i = tid; i < 384; i += NTHREADS) {
        int dp = i >> 4, rem = i & 15, c = rem >> 1, h = rem & 1;
        sW2p[i] = W2[c * DIMX + dp * 2 + h];                       // W2[c][d] -> [dp][c-pairs]
    }
    if (tid < 48) sb2[tid] = b2[tid];
    __syncthreads();

    const int y0 = by * TILE - 1;
    const int x0 = bx * TILE - 1;
    const float* xb = x + (size_t)bb * ((size_t)HW * DIMX);

    uint2* buf = sStg + warp * (64 * STG_U2);

    // ---- Stage A: balanced dual-chunk rounds with shared W1 reads ----
    // 37 chunks of 32 px. Dual rounds: (w, w+8), (16+w, 24+w); tail 32+w single.
    #pragma unroll 1
    for (int rd = 0; rd < 2; ++rd) {
        int kA = rd * 16 + warp;
        int kB = kA + 8;
        int qA0 = kA * 32, qB0 = kB * 32;

        stage_chunk(buf, xb, y0, x0, qA0, qA0 + 32, 0,  lane);
        stage_chunk(buf, xb, y0, x0, qB0, qB0 + 32, 32, lane);
        __syncwarp();

        const uint2* __restrict__ xpA = buf + lane * STG_U2;
        const uint2* __restrict__ xpB = buf + (lane + 32) * STG_U2;
        u64 acc[2][8];
        #pragma unroll
        for (int jj = 0; jj < 8; jj++) {
            u64 bj = ((const u64*)sb1)[jj];
            acc[0][jj] = bj; acc[1][jj] = bj;
        }
        #pragma unroll 3
        for (int i = 0; i < 12; i++) {
            uint2 ua = xpA[i];
            uint2 ub = xpB[i];
            float2 fa0 = unpack_h2(ua.x), fa1 = unpack_h2(ua.y);
            float2 fb0 = unpack_h2(ub.x), fb1 = unpack_h2(ub.y);
            const ulonglong2* wr = (const ulonglong2*)&sW1[i * 64];
            u64 xA, xB;
            xA = f2bcast(fa0.x); xB = f2bcast(fb0.x);
            #pragma unroll
            for (int jj = 0; jj < 4; jj++) {
                ulonglong2 w = wr[jj];
                acc[0][2*jj]   = f2fma(xA, w.x, acc[0][2*jj]);
                acc[0][2*jj+1] = f2fma(xA, w.y, acc[0][2*jj+1]);
                acc[1][2*jj]   = f2fma(xB, w.x, acc[1][2*jj]);
                acc[1][2*jj+1] = f2fma(xB, w.y, acc[1][2*jj+1]);
            }
            xA = f2bcast(fa0.y); xB = f2bcast(fb0.y);
            #pragma unroll
            for (int jj = 0; jj < 4; jj++) {
                ulonglong2 w = wr[4 + jj];
                acc[0][2*jj]   = f2fma(xA, w.x, acc[0][2*jj]);
                acc[0][2*jj+1] = f2fma(xA, w.y, acc[0][2*jj+1]);
                acc[1][2*jj]   = f2fma(xB, w.x, acc[1][2*jj]);
                acc[1][2*jj+1] = f2fma(xB, w.y, acc[1][2*jj+1]);
            }
            xA = f2bcast(fa1.x); xB = f2bcast(fb1.x);
            #pragma unroll
            for (int jj = 0; jj < 4; jj++) {
                ulonglong2 w = wr[8 + jj];
                acc[0][2*jj]   = f2fma(xA, w.x, acc[0][2*jj]);
                acc[0][2*jj+1] = f2fma(xA, w.y, acc[0][2*jj+1]);
                acc[1][2*jj]   = f2fma(xB, w.x, acc[1][2*jj]);
                acc[1][2*jj+1] = f2fma(xB, w.y, acc[1][2*jj+1]);
            }
            xA = f2bcast(fa1.y); xB = f2bcast(fb1.y);
            #pragma unroll
            for (int jj = 0; jj < 4; jj++) {
                ulonglong2 w = wr[12 + jj];
                acc[0][2*jj]   = f2fma(xA, w.x, acc[0][2*jj]);
                acc[0][2*jj+1] = f2fma(xA, w.y, acc[0][2*jj+1]);
                acc[1][2*jj]   = f2fma(xB, w.x, acc[1][2*jj]);
                acc[1][2*jj+1] = f2fma(xB, w.y, acc[1][2*jj+1]);
            }
        }
        epilogueA(acc[0], qA0 + lane, y0, x0, sNa, sNb, sX1h, sGa, sBe);
        epilogueA(acc[1], qB0 + lane, y0, x0, sNa, sNb, sX1h, sGa, sBe);
        __syncwarp();
    }

    // tail: chunks 32..36 (warps 0..4), single-pixel mode
    {
        int k = 32 + warp;
        if (k <= 36) {
            int q0 = k * 32;
            int qend = min(q0 + 32, NHALO);
            stage_chunk(buf, xb, y0, x0, q0, qend, 0, lane);
            __syncwarp();
            int q = q0 + lane;
            if (q < qend) {
                const uint2* __restrict__ xp = buf + lane * STG_U2;
                u64 acc[8];
                #pragma unroll
                for (int jj = 0; jj < 8; jj++) acc[jj] = ((const u64*)sb1)[jj];
                #pragma unroll 3
                for (int i = 0; i < 12; i++) {
                    uint2 uxv = xp[i];
                    float2 f0 = unpack_h2(uxv.x), f1 = unpack_h2(uxv.y);
                    const ulonglong2* wr = (const ulonglong2*)&sW1[i * 64];
                    u64 xv;
                    xv = f2bcast(f0.x);
                    #pragma unroll
                    for (int jj = 0; jj < 4; jj++) { ulonglong2 w = wr[jj];      acc[2*jj] = f2fma(xv, w.x, acc[2*jj]); acc[2*jj+1] = f2fma(xv, w.y, acc[2*jj+1]); }
                    xv = f2bcast(f0.y);
                    #pragma unroll
                    for (int jj = 0; jj < 4; jj++) { ulonglong2 w = wr[4 + jj];  acc[2*jj] = f2fma(xv, w.x, acc[2*jj]); acc[2*jj+1] = f2fma(xv, w.y, acc[2*jj+1]); }
                    xv = f2bcast(f1.x);
                    #pragma unroll
                    for (int jj = 0; jj < 4; jj++) { ulonglong2 w = wr[8 + jj];  acc[2*jj] = f2fma(xv, w.x, acc[2*jj]); acc[2*jj+1] = f2fma(xv, w.y, acc[2*jj+1]); }
                    xv = f2bcast(f1.y);
                    #pragma unroll
                    for (int jj = 0; jj < 4; jj++) { ulonglong2 w = wr[12 + jj]; acc[2*jj] = f2fma(xv, w.x, acc[2*jj]); acc[2*jj+1] = f2fma(xv, w.y, acc[2*jj+1]); }
                }
                epilogueA(acc, q, y0, x0, sNa, sNb, sX1h, sGa, sBe);
            }
        }
    }
    __syncthreads();

    // ---- Stage B: packed dw/pw/gate + packed GEMM2 over 2-pixel halves ----
    const int px = tid & 31;
    const int sy = tid >> 5;
    float* outb = out + (size_t)bb * ((size_t)DIMX * HW);
    const u64* dwbU = (const u64*)sDwB;
    const u64* pwbU = (const u64*)sPwB;
    const u64* sb2U = (const u64*)sb2;

    #pragma unroll
    for (int half = 0; half < 2; ++half) {
        u64 gb[16];   // broadcast-packed gates for 2 pixels x 8 channels
        #pragma unroll
        for (int r2i = 0; r2i < 2; ++r2i) {
            int py = sy * 4 + half * 2 + r2i;
            u64 s0 = dwbU[0], s1 = dwbU[1], s2 = dwbU[2], s3 = dwbU[3];
            u64 ca[4];
            #pragma unroll
            for (int dy = 0; dy < 3; dy++) {
                #pragma unroll
                for (int dx = 0; dx < 3; dx++) {
                    int hp = (py + dy) * HALO + (px + dx);
                    ulonglong2 a2 = sNa[hp];
                    ulonglong2 b2v = sNb[hp];
                    if (dy == 1 && dx == 1) { ca[0] = a2.x; ca[1] = a2.y; ca[2] = b2v.x; ca[3] = b2v.y; }
                    const ulonglong2* wt = (const ulonglong2*)&sDwT[(dy * 3 + dx) * 8];
                    ulonglong2 wa = wt[0], wb = wt[1];
                    s0 = f2fma(a2.x,  wa.x, s0);
                    s1 = f2fma(a2.y,  wa.y, s1);
                    s2 = f2fma(b2v.x, wb.x, s2);
                    s3 = f2fma(b2v.y, wb.y, s3);
                }
            }
            // pointwise conv (co-pairs packed)
            u64 chv0 = pwbU[0], chv1 = pwbU[1], chv2 = pwbU[2], chv3 = pwbU[3];
            float n[8];
            f2unpack(ca[0], n[0], n[1]);
            f2unpack(ca[1], n[2], n[3]);
            f2unpack(ca[2], n[4], n[5]);
            f2unpack(ca[3], n[6], n[7]);
            #pragma unroll
            for (int ci = 0; ci < 8; ++ci) {
                u64 nb_ = f2bcast(n[ci]);
                const ulonglong2* pwr = (const ulonglong2*)&sPwT[ci * 8];
                ulonglong2 w0 = pwr[0], w1 = pwr[1];
                chv0 = f2fma(nb_, w0.x, chv0);
                chv1 = f2fma(nb_, w0.y, chv1);
                chv2 = f2fma(nb_, w1.x, chv2);
                chv3 = f2fma(nb_, w1.y, chv3);
            }
            // gate
            uint4 u = sX1h[py * TILE + px];
            float2 f;
            u64 g2v; float ga, gbh;
            f = unpack_h2(u.x); g2v = f2mul(f2pack(f.x, f.y), f2mul(s0, chv0));
            f2unpack(g2v, ga, gbh); gb[r2i*8 + 0] = f2bcast(ga); gb[r2i*8 + 1] = f2bcast(gbh);
            f = unpack_h2(u.y); g2v = f2mul(f2pack(f.x, f.y), f2mul(s1, chv1));
            f2unpack(g2v, ga, gbh); gb[r2i*8 + 2] = f2bcast(ga); gb[r2i*8 + 3] = f2bcast(gbh);
            f = unpack_h2(u.z); g2v = f2mul(f2pack(f.x, f.y), f2mul(s2, chv2));
            f2unpack(g2v, ga, gbh); gb[r2i*8 + 4] = f2bcast(ga); gb[r2i*8 + 5] = f2bcast(gbh);
            f = unpack_h2(u.w); g2v = f2mul(f2pack(f.x, f.y), f2mul(s3, chv3));
            f2unpack(g2v, ga, gbh); gb[r2i*8 + 6] = f2bcast(ga); gb[r2i*8 + 7] = f2bcast(gbh);
        }

        // packed GEMM2: d-pairs, 2 pixels per pass
        float* op0 = outb + (size_t)((y0 + 1 + sy * 4 + half * 2) * IMG_W + (x0 + 1 + px));
        #pragma unroll 6
        for (int dp = 0; dp < 24; ++dp) {
            const ulonglong2* wv = (const ulonglong2*)&sW2p[dp * 16];
            ulonglong2 w0 = wv[0], w1 = wv[1], w2v = wv[2], w3 = wv[3];
            u64 bias2 = sb2U[dp];
            #pragma unroll
            for (int r2i = 0; r2i < 2; ++r2i) {
                const u64* gr = &gb[r2i * 8];
                u64 a = bias2;
                a = f2fma(gr[0], w0.x,  a);
                a = f2fma(gr[1], w0.y,  a);
                a = f2fma(gr[2], w1.x,  a);
                a = f2fma(gr[3], w1.y,  a);
                a = f2fma(gr[4], w2v.x, a);
                a = f2fma(gr[5], w2v.y, a);
                a = f2fma(gr[6], w3.x,  a);
                a = f2fma(gr[7], w3.y,  a);
                float v0, v1; f2unpack(a, v0, v1);
                float* od = op0 + r2i * IMG_W + (size_t)(dp * 2) * HW;
                od[0]  = v0;
                od[HW] = v1;
            }
        }
    }
}

extern "C" void kernel_launch(void* const* d_in, const int* in_sizes, int n_in,
                              void* d_out, int out_size) {
    (void)in_sizes; (void)n_in; (void)out_size;
    const float* x   = (const float*)d_in[0];
    const float* W1  = (const float*)d_in[1];
    const float* b1  = (const float*)d_in[2];
    const float* gam = (const float*)d_in[3];
    const float* bet = (const float*)d_in[4];
    const float* dww = (const float*)d_in[5];
    const float* dwb = (const float*)d_in[6];
    const float* pww = (const float*)d_in[7];
    const float* pwb = (const float*)d_in[8];
    const float* W2  = (const float*)d_in[9];
    const float* b2  = (const float*)d_in[10];
    float* out = (float*)d_out;

    const int smem_bytes = 1384 * 4                      // weights (5536)
                         + NHALO * 2 * 16                // sNa+sNb fp32 (36992)
                         + NINNER * 16                   // sX1h fp16 (16384)
                         + 8 * 64 * STG_U2 * 8;          // fp16 staging (53248)
                                                         // total 112160 B -> 2 CTA/SM
    cudaFuncSetAttribute(dclf_fused_kernel,
                         cudaFuncAttributeMaxDynamicSharedMemorySize, smem_bytes);

    dim3 grid(IMG_W / TILE, IMG_H / TILE, 16);  // 8 x 8 x B
    dclf_fused_kernel<<<grid, NTHREADS, smem_bytes>>>(
        x, W1, b1, gam, bet, dww, dwb, pww, pwb, W2, b2, out);
}

// round 13
// speedup vs baseline: 1.4485x; 1.1814x over previous
#include <cuda_runtime.h>
#include <cuda_fp16.h>
#include <cstdint>

#define DIMX     48
#define HID      16
#define CH       8
#define IMG_H    256
#define IMG_W    256
#define HW       65536
#define TILE     32
#define HALO     34
#define NHALO    (HALO*HALO)    /* 1156 */
#define NINNER   (TILE*TILE)    /* 1024 */
#define NTHREADS 256
#define STG_U2   14             /* uint2 stride per staged pixel: 112B, 16B-aligned for ldmatrix */

typedef unsigned long long u64;

// ---- packed f32x2 helpers (sm_103a FFMA2; ptxas never emits from C++) ----
__device__ __forceinline__ u64 f2pack(float lo, float hi) {
    u64 r; asm("mov.b64 %0,{%1,%2};" : "=l"(r) : "f"(lo), "f"(hi)); return r;
}
__device__ __forceinline__ u64 f2bcast(float v) {
    u64 r; asm("mov.b64 %0,{%1,%1};" : "=l"(r) : "f"(v)); return r;
}
__device__ __forceinline__ void f2unpack(u64 v, float& lo, float& hi) {
    asm("mov.b64 {%0,%1},%2;" : "=f"(lo), "=f"(hi) : "l"(v));
}
__device__ __forceinline__ u64 f2fma(u64 a, u64 b, u64 c) {
    u64 d; asm("fma.rn.f32x2 %0,%1,%2,%3;" : "=l"(d) : "l"(a), "l"(b), "l"(c)); return d;
}
__device__ __forceinline__ u64 f2mul(u64 a, u64 b) {
    u64 d; asm("mul.rn.f32x2 %0,%1,%2;" : "=l"(d) : "l"(a), "l"(b)); return d;
}
__device__ __forceinline__ u64 f2add(u64 a, u64 b) {
    u64 d; asm("add.rn.f32x2 %0,%1,%2;" : "=l"(d) : "l"(a), "l"(b)); return d;
}
__device__ __forceinline__ u64 c2(float v) {
    unsigned u = __float_as_uint(v);
    return ((u64)u << 32) | (u64)u;
}

// packed double-value GELU (exact-erf form, A&S 7.1.26 poly; MUFU parts scalar)
__device__ __forceinline__ u64 gelu2(u64 z) {
    u64 arg = f2mul(z, c2(0.70710678118654752f));
    u64 ax  = arg & 0x7FFFFFFF7FFFFFFFULL;
    u64 den = f2fma(ax, c2(0.3275911f), c2(1.0f));
    float d0, d1, t0, t1;
    f2unpack(den, d0, d1);
    asm("rcp.approx.f32 %0,%1;" : "=f"(t0) : "f"(d0));
    asm("rcp.approx.f32 %0,%1;" : "=f"(t1) : "f"(d1));
    u64 t = f2pack(t0, t1);
    u64 p = f2fma(t, c2(1.061405429f), c2(-1.453152027f));
    p = f2fma(t, p, c2(1.421413741f));
    p = f2fma(t, p, c2(-0.284496736f));
    p = f2fma(t, p, c2(0.254829592f));
    p = f2mul(p, t);
    u64 m = f2mul(ax, ax ^ 0x8000000080000000ULL);   // -ax^2
    m = f2mul(m, c2(1.4426950408889634f));
    float m0, m1, e0, e1;
    f2unpack(m, m0, m1);
    asm("ex2.approx.f32 %0,%1;" : "=f"(e0) : "f"(m0));
    asm("ex2.approx.f32 %0,%1;" : "=f"(e1) : "f"(m1));
    u64 e = f2pack(e0, e1);
    u64 r = f2fma(f2mul(p, e), c2(-1.0f), c2(1.0f));
    u64 erf = r | (arg & 0x8000000080000000ULL);
    u64 h = f2mul(z, c2(0.5f));
    return f2fma(h, erf, h);
}

__device__ __forceinline__ unsigned pack_h2(float a, float b) {
    __half2 h = __floats2half2_rn(a, b);
    return *reinterpret_cast<unsigned*>(&h);
}
__device__ __forceinline__ float2 unpack_h2(unsigned u) {
    __half2 h = *reinterpret_cast<__half2*>(&u);
    return __half22float2(h);
}

// ---- tensor-core helpers (warp-level HMMA path) ----
__device__ __forceinline__ void ldsm_x4(uint32_t& r0, uint32_t& r1, uint32_t& r2, uint32_t& r3,
                                        uint32_t addr) {
    asm volatile("ldmatrix.sync.aligned.m8n8.x4.shared.b16 {%0,%1,%2,%3},[%4];"
        : "=r"(r0), "=r"(r1), "=r"(r2), "=r"(r3) : "r"(addr) : "memory");
}
__device__ __forceinline__ void mma16816(float* c,
                                         uint32_t a0, uint32_t a1, uint32_t a2, uint32_t a3,
                                         uint32_t b0, uint32_t b1) {
    asm volatile("mma.sync.aligned.m16n8k16.row.col.f32.f16.f16.f32 "
                 "{%0,%1,%2,%3},{%4,%5,%6,%7},{%8,%9},{%0,%1,%2,%3};"
        : "+f"(c[0]), "+f"(c[1]), "+f"(c[2]), "+f"(c[3])
        : "r"(a0), "r"(a1), "r"(a2), "r"(a3), "r"(b0), "r"(b1));
}

// coalesced fp16 staging of one 32-px halo chunk into per-warp buffer
__device__ __forceinline__ void stage_chunk(uint2* buf, const float* xb,
                                            int y0, int x0, int q0, int qend, int lane)
{
    int r0 = q0 / HALO, r1 = (qend - 1) / HALO;
    #pragma unroll 1
    for (int r = r0; r <= r1; ++r) {
        int gy = y0 + r;
        if ((unsigned)gy < (unsigned)IMG_H) {
            int qs = max(q0, r * HALO), qe = min(qend, r * HALO + HALO);
            int gxs = x0 + (qs - r * HALO);
            int gxe = x0 + (qe - r * HALO);
            int cs = max(gxs, 0), ce = min(gxe, IMG_W);
            if (ce > cs) {
                int bofs = (qs - q0) + (cs - gxs);
                const float4* gp = (const float4*)(xb + ((size_t)gy * IMG_W + cs) * DIMX);
                int nf = (ce - cs) * 12;
                for (int t = lane; t < nf; t += 32) {
                    float4 g = gp[t];
                    uint2 v;
                    v.x = pack_h2(g.x, g.y);
                    v.y = pack_h2(g.z, g.w);
                    buf[(bofs + t / 12) * STG_U2 + (t % 12)] = v;
                }
            }
        }
    }
}

// per-pixel Stage-A epilogue: double-GELU + LN + halo/x1 stores (R8-proven)
__device__ __forceinline__ void epilogueA(u64* acc, int q, int y0, int x0,
                                          ulonglong2* sNa, ulonglong2* sNb, uint4* sX1h,
                                          const float* sGa, const float* sBe)
{
    int qy = q / HALO, qx = q - qy * HALO;
    int gy = y0 + qy, gx = x0 + qx;
    bool inimg = (gy >= 0) && (gy < IMG_H) && (gx >= 0) && (gx < IMG_W);
    ulonglong2 na = make_ulonglong2(0ULL, 0ULL);
    ulonglong2 nb = make_ulonglong2(0ULL, 0ULL);
    if (inimg) {
        u64 a8[8];
        #pragma unroll
        for (int jj = 0; jj < 8; jj++) a8[jj] = gelu2(gelu2(acc[jj]));

        // LayerNorm over channels 8..15 (= a8[4..7])
        u64 s2 = f2add(f2add(a8[4], a8[5]), f2add(a8[6], a8[7]));
        float sa, sb_; f2unpack(s2, sa, sb_);
        float mmean = (sa + sb_) * 0.125f;
        u64 m2 = f2bcast(mmean);
        u64 d2[4];
        u64 v2 = 0ULL;
        #pragma unroll
        for (int jj = 0; jj < 4; jj++) { d2[jj] = f2fma(m2, c2(-1.0f), a8[4 + jj]); v2 = f2fma(d2[jj], d2[jj], v2); }
        float va, vb; f2unpack(v2, va, vb);
        float rstd = rsqrtf(fmaf(va + vb, 0.125f, 1e-5f));
        u64 r2 = f2bcast(rstd);
        u64 n2[4];
        #pragma unroll
        for (int jj = 0; jj < 4; jj++)
            n2[jj] = f2fma(f2mul(d2[jj], r2), ((const u64*)sGa)[jj], ((const u64*)sBe)[jj]);
        na = make_ulonglong2(n2[0], n2[1]);
        nb = make_ulonglong2(n2[2], n2[3]);

        if (qy >= 1 && qy <= TILE && qx >= 1 && qx <= TILE) {
            int ip = (qy - 1) * TILE + (qx - 1);
            float a0, a1; uint4 u;
            f2unpack(a8[0], a0, a1); u.x = pack_h2(a0, a1);
            f2unpack(a8[1], a0, a1); u.y = pack_h2(a0, a1);
            f2unpack(a8[2], a0, a1); u.z = pack_h2(a0, a1);
            f2unpack(a8[3], a0, a1); u.w = pack_h2(a0, a1);
            sX1h[ip] = u;
        }
    }
    sNa[q] = na;
    sNb[q] = nb;
}

extern __shared__ float sm[];

__global__ void __launch_bounds__(NTHREADS, 2) dclf_fused_kernel(
    const float* __restrict__ x,   const float* __restrict__ W1,  const float* __restrict__ b1,
    const float* __restrict__ gam, const float* __restrict__ bet,
    const float* __restrict__ dww, const float* __restrict__ dwb,
    const float* __restrict__ pww, const float* __restrict__ pwb,
    const float* __restrict__ W2,  const float* __restrict__ b2,
    float* __restrict__ out)
{
    // ---- SMEM carve ----
    float* sW1h = sm;            // 384 floats = 768 fp16, W1 [k][j]
    float* sb1  = sW1h + 384;    // 16
    float* sGa  = sb1  + 16;     // 8
    float* sBe  = sGa  + 8;      // 8
    float* sDwT = sBe  + 8;      // 72  [tap*8 + c]
    float* sDwB = sDwT + 72;     // 8
    float* sPwT = sDwB + 8;      // 64  [ci*8 + co]
    float* sPwB = sPwT + 64;     // 8
    float* sW2p = sPwB + 8;      // 384 [dpair*16 + c*2 + h]
    float* sb2  = sW2p + 384;    // 48          -> 1000 floats (4000 B)
    ulonglong2* sNa  = (ulonglong2*)(sb2 + 48);  // 1156 fp32 n ch0..3
    ulonglong2* sNb  = sNa + NHALO;              // 1156 fp32 n ch4..7
    uint4*      sX1h = (uint4*)(sNb + NHALO);    // 1024 x1 fp16
    uint2*      sStg = (uint2*)(sX1h + NINNER);  // 8 warps * 32 px * 14 uint2

    const int tid  = threadIdx.x;
    const int warp = tid >> 5, lane = tid & 31;
    const int bx = blockIdx.x, by = blockIdx.y, bb = blockIdx.z;

    // ---- load / relayout weights ----
    for (int i = tid; i < 768; i += NTHREADS)
        ((__half*)sW1h)[i] = __float2half_rn(W1[i]);                // W1 [k][j] fp16
    if (tid < 16) sb1[tid] = b1[tid];
    if (tid < 8) { sGa[tid] = gam[tid]; sBe[tid] = bet[tid]; sDwB[tid] = dwb[tid]; sPwB[tid] = pwb[tid]; }
    if (tid < 72) sDwT[(tid % 9) * 8 + tid / 9] = dww[tid];         // [c][3][3] -> [tap][c]
    if (tid < 64) sPwT[(tid % 8) * 8 + tid / 8] = pww[tid];         // [co][ci] -> [ci][co]
    for (int i = tid; i < 384; i += NTHREADS) {
        int dp = i >> 4, rem = i & 15, c = rem >> 1, h = rem & 1;
        sW2p[i] = W2[c * DIMX + dp * 2 + h];                        // W2[c][d] -> [dp][c-pairs]
    }
    if (tid < 48) sb2[tid] = b2[tid];
    __syncthreads();

    // ---- persistent B-fragments for GEMM1 (W1 fp16, col-major B = [k][n]) ----
    uint32_t bfr[3][2][2];
    {
        const __half* W1h = (const __half*)sW1h;
        int kk = (lane & 3) * 2;
        int jj = lane >> 2;
        #pragma unroll
        for (int kt = 0; kt < 3; kt++) {
            #pragma unroll
            for (int nt = 0; nt < 2; nt++) {
                int k0 = kt * 16 + kk;
                int j  = nt * 8 + jj;
                __half2 h0 = __halves2half2(W1h[k0 * HID + j],       W1h[(k0 + 1) * HID + j]);
                __half2 h1 = __halves2half2(W1h[(k0 + 8) * HID + j], W1h[(k0 + 9) * HID + j]);
                bfr[kt][nt][0] = *reinterpret_cast<uint32_t*>(&h0);
                bfr[kt][nt][1] = *reinterpret_cast<uint32_t*>(&h1);
            }
        }
    }

    const int y0 = by * TILE - 1;
    const int x0 = bx * TILE - 1;
    const float* xb = x + (size_t)bb * ((size_t)HW * DIMX);

    uint2* buf = sStg + warp * (32 * STG_U2);
    uint32_t bufa = (uint32_t)__cvta_generic_to_shared(buf);

    // ---- Stage A: stage fp16 x -> ldmatrix -> HMMA GEMM1 -> epilogue ----
    // 37 chunks of 32 px; warp w handles chunks w, w+8, ... (R8 schedule)
    for (int it = 0; it < 5; ++it) {
        int k = it * 8 + warp;
        if (k > 36) break;
        int q0 = k * 32;
        int qend = min(q0 + 32, NHALO);

        // zero rows for invalid pixels (OOB or beyond NHALO) so MMA reads finite data
        int q = q0 + lane;
        {
            int qy = q / HALO, qx = q - qy * HALO;
            int gy = y0 + qy, gx = x0 + qx;
            bool pxvalid = (q < NHALO) && gy >= 0 && gy < IMG_H && gx >= 0 && gx < IMG_W;
            if (!pxvalid) {
                uint4* zp = (uint4*)(buf + (size_t)lane * STG_U2);
                uint4 z = make_uint4(0u, 0u, 0u, 0u);
                zp[0] = z; zp[1] = z; zp[2] = z; zp[3] = z; zp[4] = z; zp[5] = z;
            }
        }
        stage_chunk(buf, xb, y0, x0, q0, qend, lane);
        __syncwarp();

        // GEMM1 via HMMA: M=32 (px), N=16, K=48
        float c[2][2][4];
        {
            int j0 = (lane & 3) * 2;
            #pragma unroll
            for (int n = 0; n < 2; n++) {
                float bb0 = sb1[n * 8 + j0], bb1 = sb1[n * 8 + j0 + 1];
                c[0][n][0] = bb0; c[0][n][1] = bb1; c[0][n][2] = bb0; c[0][n][3] = bb1;
                c[1][n][0] = bb0; c[1][n][1] = bb1; c[1][n][2] = bb0; c[1][n][3] = bb1;
            }
        }
        uint32_t abase = bufa + (lane & 15) * (STG_U2 * 8) + (lane >> 4) * 16;
        #pragma unroll
        for (int m = 0; m < 2; m++) {
            #pragma unroll
            for (int kt = 0; kt < 3; kt++) {
                uint32_t a0, a1, a2, a3;
                ldsm_x4(a0, a1, a2, a3, abase + m * 16 * (STG_U2 * 8) + kt * 32);
                mma16816(c[m][0], a0, a1, a2, a3, bfr[kt][0][0], bfr[kt][0][1]);
                mma16816(c[m][1], a0, a1, a2, a3, bfr[kt][1][0], bfr[kt][1][1]);
            }
        }
        __syncwarp();

        // scatter C px-major into buf (stride 20 floats = 80 B, 16B-aligned rows)
        float* cb = (float*)buf;
        {
            int row = lane >> 2, col0 = (lane & 3) * 2;
            #pragma unroll
            for (int m = 0; m < 2; m++) {
                #pragma unroll
                for (int n = 0; n < 2; n++) {
                    int p0 = m * 16 + row;
                    *(float2*)(cb + p0 * 20 + n * 8 + col0)       = make_float2(c[m][n][0], c[m][n][1]);
                    *(float2*)(cb + (p0 + 8) * 20 + n * 8 + col0) = make_float2(c[m][n][2], c[m][n][3]);
                }
            }
        }
        __syncwarp();

        // per-lane readback + R8 epilogue
        if (q < NHALO) {
            const float4* cr = (const float4*)(cb + lane * 20);
            float4 t0 = cr[0], t1 = cr[1], t2 = cr[2], t3 = cr[3];
            u64 acc[8];
            acc[0] = f2pack(t0.x, t0.y); acc[1] = f2pack(t0.z, t0.w);
            acc[2] = f2pack(t1.x, t1.y); acc[3] = f2pack(t1.z, t1.w);
            acc[4] = f2pack(t2.x, t2.y); acc[5] = f2pack(t2.z, t2.w);
            acc[6] = f2pack(t3.x, t3.y); acc[7] = f2pack(t3.z, t3.w);
            epilogueA(acc, q, y0, x0, sNa, sNb, sX1h, sGa, sBe);
        }
        __syncwarp();
    }
    __syncthreads();

    // ---- Stage B (R8-verbatim): packed dw/pw/gate + packed GEMM2, 2-px halves ----
    const int px = tid & 31;
    const int sy = tid >> 5;
    float* outb = out + (size_t)bb * ((size_t)DIMX * HW);
    const u64* dwbU = (const u64*)sDwB;
    const u64* pwbU = (const u64*)sPwB;
    const u64* sb2U = (const u64*)sb2;

    #pragma unroll
    for (int half = 0; half < 2; ++half) {
        u64 gb[16];   // broadcast-packed gates for 2 pixels x 8 channels
        #pragma unroll
        for (int r2i = 0; r2i < 2; ++r2i) {
            int py = sy * 4 + half * 2 + r2i;
            u64 s0 = dwbU[0], s1 = dwbU[1], s2 = dwbU[2], s3 = dwbU[3];
            u64 ca[4];
            #pragma unroll
            for (int dy = 0; dy < 3; dy++) {
                #pragma unroll
                for (int dx = 0; dx < 3; dx++) {
                    int hp = (py + dy) * HALO + (px + dx);
                    ulonglong2 a2 = sNa[hp];
                    ulonglong2 b2v = sNb[hp];
                    if (dy == 1 && dx == 1) { ca[0] = a2.x; ca[1] = a2.y; ca[2] = b2v.x; ca[3] = b2v.y; }
                    const ulonglong2* wt = (const ulonglong2*)&sDwT[(dy * 3 + dx) * 8];
                    ulonglong2 wa = wt[0], wb = wt[1];
                    s0 = f2fma(a2.x,  wa.x, s0);
                    s1 = f2fma(a2.y,  wa.y, s1);
                    s2 = f2fma(b2v.x, wb.x, s2);
                    s3 = f2fma(b2v.y, wb.y, s3);
                }
            }
            // pointwise conv (co-pairs packed)
            u64 chv0 = pwbU[0], chv1 = pwbU[1], chv2 = pwbU[2], chv3 = pwbU[3];
            float n[8];
            f2unpack(ca[0], n[0], n[1]);
            f2unpack(ca[1], n[2], n[3]);
            f2unpack(ca[2], n[4], n[5]);
            f2unpack(ca[3], n[6], n[7]);
            #pragma unroll
            for (int ci = 0; ci < 8; ++ci) {
                u64 nb_ = f2bcast(n[ci]);
                const ulonglong2* pwr = (const ulonglong2*)&sPwT[ci * 8];
                ulonglong2 w0 = pwr[0], w1 = pwr[1];
                chv0 = f2fma(nb_, w0.x, chv0);
                chv1 = f2fma(nb_, w0.y, chv1);
                chv2 = f2fma(nb_, w1.x, chv2);
                chv3 = f2fma(nb_, w1.y, chv3);
            }
            // gate
            uint4 u = sX1h[py * TILE + px];
            float2 f;
            u64 g2v; float ga, gbh;
            f = unpack_h2(u.x); g2v = f2mul(f2pack(f.x, f.y), f2mul(s0, chv0));
            f2unpack(g2v, ga, gbh); gb[r2i*8 + 0] = f2bcast(ga); gb[r2i*8 + 1] = f2bcast(gbh);
            f = unpack_h2(u.y); g2v = f2mul(f2pack(f.x, f.y), f2mul(s1, chv1));
            f2unpack(g2v, ga, gbh); gb[r2i*8 + 2] = f2bcast(ga); gb[r2i*8 + 3] = f2bcast(gbh);
            f = unpack_h2(u.z); g2v = f2mul(f2pack(f.x, f.y), f2mul(s2, chv2));
            f2unpack(g2v, ga, gbh); gb[r2i*8 + 4] = f2bcast(ga); gb[r2i*8 + 5] = f2bcast(gbh);
            f = unpack_h2(u.w); g2v = f2mul(f2pack(f.x, f.y), f2mul(s3, chv3));
            f2unpack(g2v, ga, gbh); gb[r2i*8 + 6] = f2bcast(ga); gb[r2i*8 + 7] = f2bcast(gbh);
        }

        // packed GEMM2: d-pairs, 2 pixels per pass
        float* op0 = outb + (size_t)((y0 + 1 + sy * 4 + half * 2) * IMG_W + (x0 + 1 + px));
        #pragma unroll 6
        for (int dp = 0; dp < 24; ++dp) {
            const ulonglong2* wv = (const ulonglong2*)&sW2p[dp * 16];
            ulonglong2 w0 = wv[0], w1 = wv[1], w2v = wv[2], w3 = wv[3];
            u64 bias2 = sb2U[dp];
            #pragma unroll
            for (int r2i = 0; r2i < 2; ++r2i) {
                const u64* gr = &gb[r2i * 8];
                u64 a = bias2;
                a = f2fma(gr[0], w0.x,  a);
                a = f2fma(gr[1], w0.y,  a);
                a = f2fma(gr[2], w1.x,  a);
                a = f2fma(gr[3], w1.y,  a);
                a = f2fma(gr[4], w2v.x, a);
                a = f2fma(gr[5], w2v.y, a);
                a = f2fma(gr[6], w3.x,  a);
                a = f2fma(gr[7], w3.y,  a);
                float v0, v1; f2unpack(a, v0, v1);
                float* od = op0 + r2i * IMG_W + (size_t)(dp * 2) * HW;
                od[0]  = v0;
                od[HW] = v1;
            }
        }
    }
}

extern "C" void kernel_launch(void* const* d_in, const int* in_sizes, int n_in,
                              void* d_out, int out_size) {
    (void)in_sizes; (void)n_in; (void)out_size;
    const float* x   = (const float*)d_in[0];
    const float* W1  = (const float*)d_in[1];
    const float* b1  = (const float*)d_in[2];
    const float* gam = (const float*)d_in[3];
    const float* bet = (const float*)d_in[4];
    const float* dww = (const float*)d_in[5];
    const float* dwb = (const float*)d_in[6];
    const float* pww = (const float*)d_in[7];
    const float* pwb = (const float*)d_in[8];
    const float* W2  = (const float*)d_in[9];
    const float* b2  = (const float*)d_in[10];
    float* out = (float*)d_out;

    const int smem_bytes = 1000 * 4                      // weights (4000)
                         + NHALO * 2 * 16                // sNa+sNb fp32 (36992)
                         + NINNER * 16                   // sX1h fp16 (16384)
                         + 8 * 32 * STG_U2 * 8;          // fp16 staging (28672)
                                                         // total 86048 B -> 2 CTA/SM
    cudaFuncSetAttribute(dclf_fused_kernel,
                         cudaFuncAttributeMaxDynamicSharedMemorySize, smem_bytes);

    dim3 grid(IMG_W / TILE, IMG_H / TILE, 16);  // 8 x 8 x B
    dclf_fused_kernel<<<grid, NTHREADS, smem_bytes>>>(
        x, W1, b1, gam, bet, dww, dwb, pww, pwb, W2, b2, out);
}